// round 3
// baseline (speedup 1.0000x reference)
#include <cuda_runtime.h>

// CensusLoss: 5x5 census hamming distance, reflect pad, mean.
// Fixed shapes: pred/gt = (8,3,512,512) fp32.
// Single fused kernel: pair-symmetry-halved census + last-block finalize.

#define HH   512
#define WW   512
#define NIMG 24
#define TW   64
#define TH   16
#define SW   (TW + 4)      // 68
#define SH   (TH + 4)      // 20
#define NELEM 6291456.0
#define NBLOCKS ((WW/TW)*(HH/TH)*NIMG)   // 8*32*24 = 6144

__device__ unsigned int g_acc = 0;
__device__ unsigned int g_count = 0;

// jnp reflect (edge not repeated): i<0 -> -i ; i>=n -> 2n-2-i
__device__ __forceinline__ int refl(int i, int n) {
    i = (i < 0) ? -i : i;
    return (i >= n) ? (2 * n - 2 - i) : i;
}

__global__ __launch_bounds__(256)
void census_kernel(const float* __restrict__ pred, const float* __restrict__ gt,
                   float* __restrict__ out)
{
    __shared__ __align__(16) float sp[SH][SW];
    __shared__ __align__(16) float sg[SH][SW];
    __shared__ int wsum[8];

    const int img  = blockIdx.z;
    const int row0 = blockIdx.y * TH;
    const int col0 = blockIdx.x * TW;
    const float* __restrict__ p = pred + (size_t)img * HH * WW;
    const float* __restrict__ g = gt   + (size_t)img * HH * WW;

    const int tid = threadIdx.x;

    // Cooperative halo load with reflect indexing (1360 elems per tensor).
    for (int idx = tid; idx < SH * SW; idx += 256) {
        int lr = idx / SW;
        int lc = idx - lr * SW;
        int grr = refl(row0 + lr - 2, HH);
        int gcc = refl(col0 + lc - 2, WW);
        sp[lr][lc] = p[grr * WW + gcc];
        sg[lr][lc] = g[grr * WW + gcc];
    }
    __syncthreads();

    // Thread geometry: warp covers a 32-col x 4-row patch (branch is warp-uniform).
    const int lane = tid & 31;
    const int warp = tid >> 5;
    const int lx = lane & 7;          // 0..7
    const int ly = lane >> 3;         // 0..3
    const int wx = warp & 1;          // 0..1
    const int wy = warp >> 1;         // 0..3
    const int lr  = wy * 4 + ly;      // local row 0..15
    const int lcb = wx * 32 + lx * 4; // local col base 0..60
    const int gr  = row0 + lr;
    const int gcb = col0 + lcb;

    // Fast iff every pixel's +/-d neighbors (|dr|,|dc|<=2) are in-bounds.
    const int wr0 = row0 + wy * 4;
    const int wc0 = col0 + wx * 32;
    const bool fast = (wr0 >= 2) && (wr0 + 5 <= HH - 1) &&
                      (wc0 >= 2) && (wc0 + 33 <= WW - 1);

    int acc = 0;

    if (fast) {
        // Row segments: rows lr+2..lr+4, cols lcb..lcb+7 (12 x LDS.128 total).
        float P0[8], P1[8], P2[8], G0[8], G1[8], G2[8];
        {
            const float4* a;
            a = (const float4*)&sp[lr + 2][lcb]; ((float4*)P0)[0] = a[0]; ((float4*)P0)[1] = a[1];
            a = (const float4*)&sp[lr + 3][lcb]; ((float4*)P1)[0] = a[0]; ((float4*)P1)[1] = a[1];
            a = (const float4*)&sp[lr + 4][lcb]; ((float4*)P2)[0] = a[0]; ((float4*)P2)[1] = a[1];
            a = (const float4*)&sg[lr + 2][lcb]; ((float4*)G0)[0] = a[0]; ((float4*)G0)[1] = a[1];
            a = (const float4*)&sg[lr + 3][lcb]; ((float4*)G1)[0] = a[0]; ((float4*)G1)[1] = a[1];
            a = (const float4*)&sg[lr + 4][lcb]; ((float4*)G2)[0] = a[0]; ((float4*)G2)[1] = a[1];
        }
        #pragma unroll
        for (int k = 0; k < 4; ++k) {
            const float pc = P0[k + 2], gc = G0[k + 2];
            // dr=0, dc=1,2
            acc += 2 * ((P0[k + 3] < pc) ^ (G0[k + 3] < gc));
            acc += 2 * ((P0[k + 4] < pc) ^ (G0[k + 4] < gc));
            // dr=1,2 ; dc=-2..2
            #pragma unroll
            for (int d = 0; d < 5; ++d) {
                acc += 2 * ((P1[k + d] < pc) ^ (G1[k + d] < gc));
                acc += 2 * ((P2[k + d] < pc) ^ (G2[k + d] < gc));
            }
        }
    } else {
        // Halved accounting with exact boundary corrections:
        //   acc += f(x,R(x+d)) * (1 + [x+d in-bounds])
        //   acc += f(x,R(x-d))   if x-d out-of-bounds
        const signed char OFF[12][2] = {
            {0,1},{0,2},
            {1,-2},{1,-1},{1,0},{1,1},{1,2},
            {2,-2},{2,-1},{2,0},{2,1},{2,2}};
        #pragma unroll
        for (int k = 0; k < 4; ++k) {
            const int lc = lcb + k;
            const int gc = gcb + k;
            const float pc  = sp[lr + 2][lc + 2];
            const float gcv = sg[lr + 2][lc + 2];
            #pragma unroll
            for (int o = 0; o < 12; ++o) {
                const int dr = OFF[o][0], dc = OFF[o][1];
                const float pn = sp[lr + 2 + dr][lc + 2 + dc];
                const float gn = sg[lr + 2 + dr][lc + 2 + dc];
                const int f1 = (pn < pc) ^ (gn < gcv);
                const bool inb1 = ((unsigned)(gr + dr) < HH) && ((unsigned)(gc + dc) < WW);
                acc += f1 + (inb1 ? f1 : 0);
                const bool inb2 = ((unsigned)(gr - dr) < HH) && ((unsigned)(gc - dc) < WW);
                if (!inb2) {
                    const float pn2 = sp[lr + 2 - dr][lc + 2 - dc];
                    const float gn2 = sg[lr + 2 - dr][lc + 2 - dc];
                    acc += (pn2 < pc) ^ (gn2 < gcv);
                }
            }
        }
    }

    // Warp reduce (exact integer)
    #pragma unroll
    for (int o = 16; o; o >>= 1)
        acc += __shfl_xor_sync(0xffffffffu, acc, o);
    if (lane == 0) wsum[warp] = acc;
    __syncthreads();

    if (tid == 0) {
        int s = 0;
        #pragma unroll
        for (int w = 0; w < 8; ++w) s += wsum[w];
        atomicAdd(&g_acc, (unsigned)s);
        __threadfence();
        unsigned t = atomicAdd(&g_count, 1u);
        if (t == NBLOCKS - 1) {
            __threadfence();
            unsigned total = atomicExch(&g_acc, 0u);  // read + reset for next replay
            out[0] = (float)((double)total / NELEM);
            g_count = 0;                               // reset counter for next replay
        }
    }
}

extern "C" void kernel_launch(void* const* d_in, const int* in_sizes, int n_in,
                              void* d_out, int out_size)
{
    const float* pred = (const float*)d_in[0];
    const float* gt   = (const float*)d_in[1];
    float* out        = (float*)d_out;

    dim3 grid(WW / TW, HH / TH, NIMG);   // (8, 32, 24)
    census_kernel<<<grid, 256>>>(pred, gt, out);
}

// round 7
// speedup vs baseline: 1.0999x; 1.0999x over previous
#include <cuda_runtime.h>

// CensusLoss: 5x5 census hamming distance, reflect pad, mean.
// Fixed shapes: pred/gt = (8,3,512,512) fp32.
// Halved offset set (weight 2) for all pixels + global boundary correction C:
//   Total = 2 * sum_x sum_{d in D12} f(x, R(x+d)) + C
//   C = sum_{x: x-d OOB} f(x,R(x-d)) - sum_{x: x+d OOB} f(x,R(x+d))   (strip only)

#define HH   512
#define WW   512
#define NIMG 24
#define TW   128
#define TH   8
#define SW   (TW + 4)      // 132
#define SH   (TH + 2)      // 10 (rows r .. r+9; only downward halo needed)
#define NELEM 6291456.0
#define MAIN_BLOCKS ((WW/TW)*(HH/TH)*NIMG)   // 4*64*24 = 6144
#define CORR_BLOCKS (4*NIMG)                  // 96
#define TOTAL_BLOCKS (MAIN_BLOCKS + CORR_BLOCKS)
#define STRIP 4080                            // boundary pixels per image

__device__ unsigned int g_acc = 0;
__device__ unsigned int g_cnt = 0;

// jnp reflect (edge not repeated): i<0 -> -i ; i>=n -> 2n-2-i
__device__ __forceinline__ int refl(int i, int n) {
    i = (i < 0) ? -i : i;
    return (i >= n) ? (2 * n - 2 - i) : i;
}

__global__ __launch_bounds__(256)
void census_kernel(const float* __restrict__ pred, const float* __restrict__ gt,
                   float* __restrict__ out)
{
    __shared__ __align__(16) float sp[SH][SW];
    __shared__ __align__(16) float sg[SH][SW];
    __shared__ int wsum[8];

    const int tid = threadIdx.x;
    const int img = blockIdx.z;
    const float* __restrict__ p = pred + (size_t)img * HH * WW;
    const float* __restrict__ g = gt   + (size_t)img * HH * WW;

    int contrib = 0;

    if (blockIdx.y < HH / TH) {
        // ---------------- main halved census over a 128x8 tile ----------------
        const int row0 = blockIdx.y * TH;
        const int col0 = blockIdx.x * TW;

        // Halo: rows row0..row0+9 (reflect only at bottom), cols col0-2..col0+129.
        for (int idx = tid; idx < SH * SW; idx += 256) {
            int lr = idx / SW;
            int lc = idx - lr * SW;
            int r = row0 + lr; r = (r >= HH) ? (2 * HH - 2 - r) : r;
            int c = refl(col0 + lc - 2, WW);
            sp[lr][lc] = p[r * WW + c];
            sg[lr][lc] = g[r * WW + c];
        }
        __syncthreads();

        const int ty = tid >> 5;          // warp = output row
        const int bx = (tid & 31) * 4;    // 4-px micro-tile; smem centers at bx+2..bx+5

        float p0[8], g0[8], p1[8], g1[8], p2[8], g2[8];
        ((float4*)p0)[0] = *(const float4*)&sp[ty][bx];     ((float4*)p0)[1] = *(const float4*)&sp[ty][bx + 4];
        ((float4*)g0)[0] = *(const float4*)&sg[ty][bx];     ((float4*)g0)[1] = *(const float4*)&sg[ty][bx + 4];
        ((float4*)p1)[0] = *(const float4*)&sp[ty + 1][bx]; ((float4*)p1)[1] = *(const float4*)&sp[ty + 1][bx + 4];
        ((float4*)g1)[0] = *(const float4*)&sg[ty + 1][bx]; ((float4*)g1)[1] = *(const float4*)&sg[ty + 1][bx + 4];
        ((float4*)p2)[0] = *(const float4*)&sp[ty + 2][bx]; ((float4*)p2)[1] = *(const float4*)&sp[ty + 2][bx + 4];
        ((float4*)g2)[0] = *(const float4*)&sg[ty + 2][bx]; ((float4*)g2)[1] = *(const float4*)&sg[ty + 2][bx + 4];

        int acc = 0;
        #pragma unroll
        for (int k = 0; k < 4; ++k) {
            const float pc = p0[k + 2], gc = g0[k + 2];
            // d = (0,1), (0,2)
            acc += (p0[k + 3] < pc) ^ (g0[k + 3] < gc);
            acc += (p0[k + 4] < pc) ^ (g0[k + 4] < gc);
            // d = (1,-2..2), (2,-2..2)
            #pragma unroll
            for (int d = 0; d < 5; ++d) {
                acc += (p1[k + d] < pc) ^ (g1[k + d] < gc);
                acc += (p2[k + d] < pc) ^ (g2[k + d] < gc);
            }
        }
        contrib = 2 * acc;
    } else {
        // ---------------- boundary correction over the 2-wide strip ----------------
        const int DR[12] = {0, 0, 1, 1, 1, 1, 1, 2, 2, 2, 2, 2};
        const int DC[12] = {1, 2,-2,-1, 0, 1, 2,-2,-1, 0, 1, 2};
        int C = 0;
        for (int s = blockIdx.x * 256 + tid; s < STRIP; s += 1024) {
            int r, c;
            if (s < 2048) {            // rows {0,1,510,511}, all cols
                int ri = s >> 9;
                r = (ri < 2) ? ri : (508 + ri);
                c = s & 511;
            } else {                   // rows 2..509, cols {0,1,510,511}
                int t = s - 2048;
                int ci = t & 3;
                c = (ci < 2) ? ci : (508 + ci);
                r = 2 + (t >> 2);
            }
            const float pc = p[r * WW + c];
            const float gc = g[r * WW + c];
            #pragma unroll
            for (int o = 0; o < 12; ++o) {
                const int dr = DR[o], dc = DC[o];
                int rm = r - dr, cm = c - dc;
                if ((unsigned)rm >= HH || (unsigned)cm >= WW) {
                    int rr = refl(rm, HH) * WW + refl(cm, WW);
                    C += (p[rr] < pc) ^ (g[rr] < gc);
                }
                int rp = r + dr, cp = c + dc;
                if ((unsigned)rp >= HH || (unsigned)cp >= WW) {
                    int rr = refl(rp, HH) * WW + refl(cp, WW);
                    C -= (p[rr] < pc) ^ (g[rr] < gc);
                }
            }
        }
        contrib = C;   // may be negative; unsigned wraparound is exact mod 2^32
    }

    // ---------------- exact integer reduction + last-block finalize ----------------
    #pragma unroll
    for (int o = 16; o; o >>= 1)
        contrib += __shfl_xor_sync(0xffffffffu, contrib, o);
    if ((tid & 31) == 0) wsum[tid >> 5] = contrib;
    __syncthreads();

    if (tid == 0) {
        int s = 0;
        #pragma unroll
        for (int w = 0; w < 8; ++w) s += wsum[w];
        atomicAdd(&g_acc, (unsigned)s);
        __threadfence();
        unsigned t = atomicAdd(&g_cnt, 1u);
        if (t == TOTAL_BLOCKS - 1) {
            __threadfence();
            unsigned total = atomicExch(&g_acc, 0u);   // read + reset for next replay
            out[0] = (float)((double)total / NELEM);
            g_cnt = 0;                                  // reset for next replay
        }
    }
}

extern "C" void kernel_launch(void* const* d_in, const int* in_sizes, int n_in,
                              void* d_out, int out_size)
{
    const float* pred = (const float*)d_in[0];
    const float* gt   = (const float*)d_in[1];
    float* out        = (float*)d_out;

    dim3 grid(WW / TW, HH / TH + 1, NIMG);   // (4, 65, 24): y==64 -> correction blocks
    census_kernel<<<grid, 256>>>(pred, gt, out);
}

// round 8
// speedup vs baseline: 1.2526x; 1.1388x over previous
#include <cuda_runtime.h>

// CensusLoss: 5x5 census hamming distance, reflect pad, mean.
// Fixed shapes: pred/gt = (8,3,512,512) fp32, values in [0,1).
// Total = 2 * sum_x sum_{d in D12} f(x, R(x+d)) + C   (C = boundary correction strip)
// f computed predicate-free via sign bits: (a<b) == sign(a-b) for positive floats.

#define HH   512
#define WW   512
#define NIMG 24
#define TW   128
#define TH   8
#define SW   (TW + 4)      // 132
#define SH   (TH + 2)      // 10
#define NELEM 6291456.0
#define MAIN_BLOCKS ((WW/TW)*(HH/TH)*NIMG)   // 6144
#define CORR_BLOCKS (4*NIMG)                  // 96
#define TOTAL_BLOCKS (MAIN_BLOCKS + CORR_BLOCKS)
#define STRIP 4080

__device__ unsigned int g_acc = 0;
__device__ unsigned int g_cnt = 0;

__device__ __forceinline__ int refl(int i, int n) {
    i = (i < 0) ? -i : i;
    return (i >= n) ? (2 * n - 2 - i) : i;
}

// sign bit of (a-b) XOR sign bit of (c-d)  ==  (a<b) ^ (c<d) for positive floats
__device__ __forceinline__ unsigned sb2(float a, float b, float c, float d) {
    return (unsigned)(__float_as_int(a - b) ^ __float_as_int(c - d)) >> 31;
}

__global__ __launch_bounds__(256, 6)
void census_kernel(const float* __restrict__ pred, const float* __restrict__ gt,
                   float* __restrict__ out)
{
    __shared__ __align__(16) float sp[SH][SW];
    __shared__ __align__(16) float sg[SH][SW];
    __shared__ int wsum[8];

    const int tid = threadIdx.x;
    const int img = blockIdx.z;
    const float* __restrict__ p = pred + (size_t)img * HH * WW;
    const float* __restrict__ g = gt   + (size_t)img * HH * WW;

    int contrib = 0;

    if (blockIdx.y < HH / TH) {
        const int row0 = blockIdx.y * TH;
        const int col0 = blockIdx.x * TW;

        // -------- halo load: rows row0..row0+9, cols col0-2..col0+129 --------
        const bool interior = (blockIdx.x > 0) && (blockIdx.x < 3) && (blockIdx.y < 63);
        if (interior) {
            // vectorized, no reflect: 660 float2 per tensor
            const float* pb = p + row0 * WW + (col0 - 2);
            const float* gb = g + row0 * WW + (col0 - 2);
            for (int idx = tid; idx < SH * 66; idx += 256) {
                int lr = idx / 66;
                int lc2 = idx - lr * 66;
                float2 vp = *(const float2*)(pb + lr * WW + 2 * lc2);
                float2 vg = *(const float2*)(gb + lr * WW + 2 * lc2);
                *(float2*)&sp[lr][2 * lc2] = vp;
                *(float2*)&sg[lr][2 * lc2] = vg;
            }
        } else {
            for (int idx = tid; idx < SH * SW; idx += 256) {
                int lr = idx / SW;
                int lc = idx - lr * SW;
                int r = row0 + lr; r = (r >= HH) ? (2 * HH - 2 - r) : r;
                int c = refl(col0 + lc - 2, WW);
                sp[lr][lc] = p[r * WW + c];
                sg[lr][lc] = g[r * WW + c];
            }
        }
        __syncthreads();

        // -------- halved census: warp = row, thread = 4 px --------
        const int ty = tid >> 5;
        const int bx = (tid & 31) * 4;

        float P[8], G[8];
        int acc0 = 0, acc1 = 0;

        // row dr=0: provides centers + offsets (0,1),(0,2)
        ((float4*)P)[0] = *(const float4*)&sp[ty][bx];
        ((float4*)P)[1] = *(const float4*)&sp[ty][bx + 4];
        ((float4*)G)[0] = *(const float4*)&sg[ty][bx];
        ((float4*)G)[1] = *(const float4*)&sg[ty][bx + 4];

        float pc[4], gc[4];
        #pragma unroll
        for (int k = 0; k < 4; ++k) { pc[k] = P[k + 2]; gc[k] = G[k + 2]; }

        #pragma unroll
        for (int k = 0; k < 4; ++k) {
            acc0 += sb2(P[k + 3], pc[k], G[k + 3], gc[k]);
            acc1 += sb2(P[k + 4], pc[k], G[k + 4], gc[k]);
        }

        // rows dr=1,2: offsets dc=-2..2 (reuse P/G arrays -> low register pressure)
        #pragma unroll
        for (int dr = 1; dr <= 2; ++dr) {
            ((float4*)P)[0] = *(const float4*)&sp[ty + dr][bx];
            ((float4*)P)[1] = *(const float4*)&sp[ty + dr][bx + 4];
            ((float4*)G)[0] = *(const float4*)&sg[ty + dr][bx];
            ((float4*)G)[1] = *(const float4*)&sg[ty + dr][bx + 4];
            #pragma unroll
            for (int k = 0; k < 4; ++k) {
                acc0 += sb2(P[k + 0], pc[k], G[k + 0], gc[k]);
                acc1 += sb2(P[k + 1], pc[k], G[k + 1], gc[k]);
                acc0 += sb2(P[k + 2], pc[k], G[k + 2], gc[k]);
                acc1 += sb2(P[k + 3], pc[k], G[k + 3], gc[k]);
                acc0 += sb2(P[k + 4], pc[k], G[k + 4], gc[k]);
            }
        }
        contrib = 2 * (acc0 + acc1);
    } else {
        // -------- boundary correction strip --------
        const int DR[12] = {0, 0, 1, 1, 1, 1, 1, 2, 2, 2, 2, 2};
        const int DC[12] = {1, 2,-2,-1, 0, 1, 2,-2,-1, 0, 1, 2};
        int C = 0;
        for (int s = blockIdx.x * 256 + tid; s < STRIP; s += 1024) {
            int r, c;
            if (s < 2048) {
                int ri = s >> 9;
                r = (ri < 2) ? ri : (508 + ri);
                c = s & 511;
            } else {
                int t = s - 2048;
                int ci = t & 3;
                c = (ci < 2) ? ci : (508 + ci);
                r = 2 + (t >> 2);
            }
            const float pcv = p[r * WW + c];
            const float gcv = g[r * WW + c];
            #pragma unroll
            for (int o = 0; o < 12; ++o) {
                const int dr = DR[o], dc = DC[o];
                int rm = r - dr, cm = c - dc;
                if ((unsigned)rm >= HH || (unsigned)cm >= WW) {
                    int rr = refl(rm, HH) * WW + refl(cm, WW);
                    C += (int)sb2(p[rr], pcv, g[rr], gcv);
                }
                int rp = r + dr, cp = c + dc;
                if ((unsigned)rp >= HH || (unsigned)cp >= WW) {
                    int rr = refl(rp, HH) * WW + refl(cp, WW);
                    C -= (int)sb2(p[rr], pcv, g[rr], gcv);
                }
            }
        }
        contrib = C;
    }

    // -------- exact integer reduction + last-block finalize --------
    contrib = __reduce_add_sync(0xffffffffu, contrib);
    if ((tid & 31) == 0) wsum[tid >> 5] = contrib;
    __syncthreads();

    if (tid == 0) {
        int s = 0;
        #pragma unroll
        for (int w = 0; w < 8; ++w) s += wsum[w];
        atomicAdd(&g_acc, (unsigned)s);
        __threadfence();
        unsigned t = atomicAdd(&g_cnt, 1u);
        if (t == TOTAL_BLOCKS - 1) {
            __threadfence();
            unsigned total = atomicExch(&g_acc, 0u);
            out[0] = (float)((double)total / NELEM);
            g_cnt = 0;
        }
    }
}

extern "C" void kernel_launch(void* const* d_in, const int* in_sizes, int n_in,
                              void* d_out, int out_size)
{
    const float* pred = (const float*)d_in[0];
    const float* gt   = (const float*)d_in[1];
    float* out        = (float*)d_out;

    dim3 grid(WW / TW, HH / TH + 1, NIMG);   // (4, 65, 24)
    census_kernel<<<grid, 256>>>(pred, gt, out);
}